// round 6
// baseline (speedup 1.0000x reference)
#include <cuda_runtime.h>
#include <cstdint>

// ---------------- problem constants ----------------
#define C_CORES 64
#define D_EMB   128
#define CD      (C_CORES * D_EMB)     // 8192 floats = 32 KB per table

// ---------------- geometry ----------------
#define TABLES  6                     // 32 KB tables per block (192 KB)
#define TPB     384                   // 12 warps = 6 tables x 2 warps
#define UNR     16                    // rows per pipelined batch

// ---------------- global scratch (zero-init; kernel restores zeros) ------
__device__ unsigned int g_tab[CD];      // encoded segment-max table
__device__ unsigned int g_mask32[2];    // core-seen bitmask
__device__ int g_a1, g_d1, g_a3, g_d3;  // self-cleaning barrier counters

// order-preserving float <-> uint encoding (enc(x) != 0 for all finite x)
__device__ __forceinline__ unsigned int enc(float f) {
    unsigned int u = __float_as_uint(f);
    return (u & 0x80000000u) ? ~u : (u | 0x80000000u);
}
__device__ __forceinline__ float dec(unsigned int u) {
    u = (u & 0x80000000u) ? (u & 0x7fffffffu) : ~u;
    return __uint_as_float(u);
}
__device__ __forceinline__ float neg_inf() { return __int_as_float(0xff800000); }

__global__ __launch_bounds__(TPB, 1)
void fused_all(const int*   __restrict__ assign,
               const float* __restrict__ emb,
               const float* __restrict__ padding_emb,
               const float* __restrict__ core_con,
               const float* __restrict__ W_self,
               const float* __restrict__ W_msg,
               const float* __restrict__ bvec,
               float*       __restrict__ out,
               int Q, int chunk)
{
    extern __shared__ float sm[];            // 192 KB: tables, later epilogue
    __shared__ unsigned char s_seen[C_CORES];

    const int tid  = threadIdx.x;
    const int wid  = tid >> 5;               // 0..11
    const int lane = tid & 31;
    const int grid = gridDim.x;

    // ============ phase 1: pipelined shared-table segment max ============
    {
        const int tbl  = wid >> 1;           // table 0..5
        const int half = wid & 1;            // column half
        float* tab = sm + tbl * CD + half * 64 + lane * 2;   // owned float2 slot base

        // init tables to -inf
        float4 ninf4 = make_float4(neg_inf(), neg_inf(), neg_inf(), neg_inf());
        float4* s4 = (float4*)sm;
        for (int i = tid; i < TABLES * CD / 4; i += TPB) s4[i] = ninf4;
        if (tid < C_CORES) s_seen[tid] = 0;
        __syncthreads();

        const int ngroups = grid * TABLES;
        const int rgid    = blockIdx.x * TABLES + tbl;
        const int q0      = rgid * chunk;
        const int q1e     = q0 + chunk;
        const int q1      = (q1e < Q) ? q1e : Q;

        const float2* e2   = (const float2*)emb;
        const int     col2 = half * 32 + lane;       // float2 column 0..63
        const bool    flag = (lane == 0 && half == 0);

        if (q0 < Q) {
            const int nrows = q1 - q0;
            const int nfull = nrows / UNR;

            int    a0[UNR]; float2 v0[UNR];
            int    a1[UNR]; float2 v1[UNR];

            // prologue: load batch 0 (unguarded if full)
            if (nfull > 0) {
#pragma unroll
                for (int u = 0; u < UNR; u++) {
                    a0[u] = __ldg(assign + q0 + u);
                    v0[u] = __ldg(e2 + (size_t)(q0 + u) * 64 + col2);
                }
            }

            for (int b = 0; b < nfull; b++) {
                // prefetch next full batch BEFORE consuming current
                if (b + 1 < nfull) {
                    const int qn = q0 + (b + 1) * UNR;
#pragma unroll
                    for (int u = 0; u < UNR; u++) {
                        a1[u] = __ldg(assign + qn + u);
                        v1[u] = __ldg(e2 + (size_t)(qn + u) * 64 + col2);
                    }
                }
                // RMW current batch into the table (race-free: owned columns)
#pragma unroll
                for (int u = 0; u < UNR; u++) {
                    float2* p = (float2*)(tab + a0[u] * D_EMB);
                    float2 o = *p;
                    o.x = fmaxf(o.x, v0[u].x);
                    o.y = fmaxf(o.y, v0[u].y);
                    *p = o;
                    if (flag) s_seen[a0[u]] = 1;
                }
#pragma unroll
                for (int u = 0; u < UNR; u++) { a0[u] = a1[u]; v0[u] = v1[u]; }
            }

            // guarded tail
            for (int q = q0 + nfull * UNR; q < q1; q++) {
                int c = __ldg(assign + q);
                float2 v = __ldg(e2 + (size_t)q * 64 + col2);
                float2* p = (float2*)(tab + c * D_EMB);
                float2 o = *p;
                o.x = fmaxf(o.x, v.x);
                o.y = fmaxf(o.y, v.y);
                *p = o;
                if (flag) s_seen[c] = 1;
            }
        }
        __syncthreads();

        // merge 6 tables -> encoded global fold (no-return REDG.MAX)
        for (int i = tid; i < CD / 4; i += TPB) {
            float4 m = s4[i];
#pragma unroll
            for (int r = 1; r < TABLES; r++) {
                float4 o = s4[r * (CD / 4) + i];
                m.x = fmaxf(m.x, o.x); m.y = fmaxf(m.y, o.y);
                m.z = fmaxf(m.z, o.z); m.w = fmaxf(m.w, o.w);
            }
            unsigned int* gp = g_tab + i * 4;
            atomicMax(gp + 0, enc(m.x));
            atomicMax(gp + 1, enc(m.y));
            atomicMax(gp + 2, enc(m.z));
            atomicMax(gp + 3, enc(m.w));
        }
        if (wid == 0) {
            unsigned b0 = __ballot_sync(0xffffffffu, s_seen[lane]      != 0);
            unsigned b1 = __ballot_sync(0xffffffffu, s_seen[lane + 32] != 0);
            if (lane == 0) {
                if (b0) atomicOr(&g_mask32[0], b0);
                if (b1) atomicOr(&g_mask32[1], b1);
            }
        }
    }

    // ============ grid barrier #1 (self-cleaning) =========================
    __threadfence();
    __syncthreads();
    if (blockIdx.x >= C_CORES) {             // non-epilogue blocks: arrive+exit
        if (tid == 0) atomicAdd(&g_a1, 1);
        return;
    }
    if (tid == 0) {
        atomicAdd(&g_a1, 1);
        while (atomicAdd(&g_a1, 0) < grid) __nanosleep(64);
        if (atomicAdd(&g_d1, 1) == C_CORES - 1) {
            atomicExch(&g_a1, 0);
            atomicExch(&g_d1, 0);
        }
        __threadfence();
    }
    __syncthreads();

    // ============ phase 2: decode E + fused GNN (smem reused) =============
    float (*sE)[D_EMB] = (float(*)[D_EMB])sm;        // 32 KB
    float* sMp = sm + CD;                            // 3 x 128
    float* sM  = sm + CD + 3 * D_EMB;                // 128
    float* sO  = sm + CD + 4 * D_EMB;                // 3 x 128

    const int c = blockIdx.x;
    const int t = tid & 127;
    const int s = tid >> 7;                          // 0..2

    unsigned long long mask =
        ((unsigned long long)g_mask32[1] << 32) | (unsigned long long)g_mask32[0];
    {
        const float pad = __ldg(&padding_emb[t]);
        for (int j = s; j < C_CORES; j += 3) {
            unsigned int u = g_tab[j * D_EMB + t];
            sE[j][t] = ((mask >> j) & 1ull) ? dec(u) : pad;
        }
    }
    __syncthreads();

    // ---- barrier #3 among the 64 epilogue blocks (all reads of g_tab done)
    if (tid == 0) {
        atomicAdd(&g_a3, 1);
        while (atomicAdd(&g_a3, 0) < C_CORES) __nanosleep(64);
        if (atomicAdd(&g_d3, 1) == C_CORES - 1) {
            atomicExch(&g_a3, 0);
            atomicExch(&g_d3, 0);
        }
        __threadfence();
    }
    __syncthreads();

    // restore zero state for next graph replay
    if (tid < 32) ((uint4*)g_tab)[c * 32 + tid] = make_uint4(0, 0, 0, 0);
    if (c == 0 && tid == 32) { g_mask32[0] = 0u; g_mask32[1] = 0u; }

    // Msum[t] = sum_j con[c,j] * E[j,t]
    {
        float a = 0.f;
        for (int j = s; j < C_CORES; j += 3)
            a = fmaf(__ldg(&core_con[c * C_CORES + j]), sE[j][t], a);
        sMp[s * D_EMB + t] = a;
    }
    __syncthreads();
    if (s == 0)
        sM[t] = sMp[t] + sMp[D_EMB + t] + sMp[2 * D_EMB + t];
    __syncthreads();

    // out = relu(E@W_self + Msum@W_msg + b)
    {
        float a0 = 0.f, a1 = 0.f;
        for (int k = s; k < D_EMB; k += 3) {
            a0 = fmaf(sE[c][k], __ldg(&W_self[k * D_EMB + t]), a0);
            a1 = fmaf(sM[k],    __ldg(&W_msg [k * D_EMB + t]), a1);
        }
        sO[s * D_EMB + t] = a0 + a1;
    }
    __syncthreads();
    if (s == 0) {
        float r = sO[t] + sO[D_EMB + t] + sO[2 * D_EMB + t] + __ldg(&bvec[t]);
        out[c * D_EMB + t] = fmaxf(r, 0.f);
    }
}

// ---------------- launch ----------------
extern "C" void kernel_launch(void* const* d_in, const int* in_sizes, int n_in,
                              void* d_out, int out_size)
{
    const int*   assign      = (const int*)  d_in[0];
    const float* emb         = (const float*)d_in[1];
    const float* padding_emb = (const float*)d_in[2];
    const float* core_con    = (const float*)d_in[3];
    const float* W_self      = (const float*)d_in[4];
    const float* W_msg       = (const float*)d_in[5];
    const float* bvec        = (const float*)d_in[6];
    float* out = (float*)d_out;

    const int Q = in_sizes[0];

    int nsm = 148;
    cudaDeviceGetAttribute(&nsm, cudaDevAttrMultiProcessorCount, 0);
    if (nsm < C_CORES) nsm = C_CORES;            // barrier needs >= 64 blocks

    const int ngroups = nsm * TABLES;
    const int chunk   = (Q + ngroups - 1) / ngroups;

    const int smem = TABLES * CD * (int)sizeof(float);   // 192 KB
    cudaFuncSetAttribute(fused_all, cudaFuncAttributeMaxDynamicSharedMemorySize, smem);

    fused_all<<<nsm, TPB, smem>>>(assign, emb, padding_emb, core_con,
                                  W_self, W_msg, bvec, out, Q, chunk);
}